// round 10
// baseline (speedup 1.0000x reference)
#include <cuda_runtime.h>
#include <cuda_fp16.h>
#include <cstdint>

#define NF  16384   // n_features
#define ND  768     // d_model
#define NBS 1024    // B*S
#define NM  262144  // n_connections

// Scratch (device globals — no cudaMalloc allowed)
__device__ __align__(16) __half g_decH[(size_t)NF * ND];   // up_decoder transposed [F, D] fp16
__device__ __align__(16) __half g_upH [(size_t)NF * NBS];  // up_facts transposed  [F, BS] fp16
__device__ __align__(16) float  g_vals[NM];
__device__ int g_seg[NF + 1];

// ---------------------------------------------------------------------------
// 32x32 tiled transpose fp32 -> fp16
// ---------------------------------------------------------------------------
__global__ void transpose32_h(const float* __restrict__ in, __half* __restrict__ out,
                              int rows, int cols) {
    __shared__ float tile[32][33];
    int c0 = blockIdx.x * 32;
    int r0 = blockIdx.y * 32;
    int x = threadIdx.x, y = threadIdx.y;
#pragma unroll
    for (int k = 0; k < 32; k += 8)
        tile[y + k][x] = in[(size_t)(r0 + y + k) * cols + (c0 + x)];
    __syncthreads();
#pragma unroll
    for (int k = 0; k < 32; k += 8)
        out[(size_t)(c0 + y + k) * rows + (r0 + x)] = __float2half_rn(tile[x][y + k]);
}

// ---------------------------------------------------------------------------
// Segment boundaries: g_seg[f] = first m with i_indices[m] >= f (i sorted).
// ---------------------------------------------------------------------------
__global__ void segstart_kernel(const int* __restrict__ iidx) {
    int f = blockIdx.x * blockDim.x + threadIdx.x;
    if (f > NF) return;
    int lo = 0, hi = NM;
    while (lo < hi) {
        int mid = (lo + hi) >> 1;
        if (iidx[mid] < f) lo = mid + 1; else hi = mid;
    }
    g_seg[f] = lo;
}

// ---------------------------------------------------------------------------
// values v5: warp per VG=16 consecutive connections; fp32 Enc row cached in
// registers across equal sorted i (avg run 16 => Enc stream ~98MB).
// fp16 Dec rows (403MB L2 stream, the floor).
// ---------------------------------------------------------------------------
#define VG 16
__device__ __forceinline__ float dot8(float4 a_lo, float4 a_hi, float4 hraw, float s) {
    const __half2* h = (const __half2*)&hraw;
    float2 u0 = __half22float2(h[0]);
    float2 u1 = __half22float2(h[1]);
    float2 u2 = __half22float2(h[2]);
    float2 u3 = __half22float2(h[3]);
    s += a_lo.x * u0.x + a_lo.y * u0.y + a_lo.z * u1.x + a_lo.w * u1.y;
    s += a_hi.x * u2.x + a_hi.y * u2.y + a_hi.z * u3.x + a_hi.w * u3.y;
    return s;
}

__global__ void values_kernel(const float* __restrict__ enc,
                              const int* __restrict__ iidx,
                              const int* __restrict__ jidx) {
    int warp = (blockIdx.x * blockDim.x + threadIdx.x) >> 5;
    int lane = threadIdx.x & 31;
    int m0 = warp * VG;
    if (m0 >= NM) return;

    float4 a0, a1, a2, a3, a4, a5;
    int prev_i = -1;

#pragma unroll
    for (int g = 0; g < VG; g++) {
        int m = m0 + g;
        int i = iidx[m];
        int j = jidx[m];
        if (i != prev_i) {
            const float4* ap = (const float4*)(enc + (size_t)i * ND);
            a0 = ap[2 * lane];       a1 = ap[2 * lane + 1];
            a2 = ap[2 * lane + 64];  a3 = ap[2 * lane + 65];
            a4 = ap[2 * lane + 128]; a5 = ap[2 * lane + 129];
            prev_i = i;
        }
        const float4* bp = (const float4*)(g_decH + (size_t)j * ND);
        float4 q0 = bp[lane];
        float4 q1 = bp[lane + 32];
        float4 q2 = bp[lane + 64];

        float s = 0.f;
        s = dot8(a0, a1, q0, s);
        s = dot8(a2, a3, q1, s);
        s = dot8(a4, a5, q2, s);

#pragma unroll
        for (int off = 16; off; off >>= 1)
            s += __shfl_xor_sync(0xFFFFFFFFu, s, off);
        if (lane == 0) g_vals[m] = s;
    }
}

// ---------------------------------------------------------------------------
// Scatter v7: fused segment-reduce + output transpose.
// CTA = TF=8 features x full 1024 bs. 256 threads = 4 groups x 64:
//   group g handles features 2g, 2g+1; thread u (0..63) owns columns
//   16u..16u+15 -> TWO independent float4 loads (32B) per connection;
//   64 x 32B = 2KB full-row wavefront. Branch-free inner loops, unroll 4
//   => 8 LDG.128 in flight per thread; 4 independent walks per CTA.
// Output staged in padded smem tile, written directly in out[bs,f] layout.
// ---------------------------------------------------------------------------
#define TF    8
#define TROW  (NBS + 4)
#define SSTG  512

__device__ __forceinline__ void fma8(float* a, float v, float4 raw) {
    const __half2* h = (const __half2*)&raw;
    float2 u0 = __half22float2(h[0]);
    float2 u1 = __half22float2(h[1]);
    float2 u2 = __half22float2(h[2]);
    float2 u3 = __half22float2(h[3]);
    a[0] += v * u0.x; a[1] += v * u0.y;
    a[2] += v * u1.x; a[3] += v * u1.y;
    a[4] += v * u2.x; a[5] += v * u2.y;
    a[6] += v * u3.x; a[7] += v * u3.y;
}

__global__ void __launch_bounds__(256) scatter_kernel(const int* __restrict__ jidx,
                                                      float* __restrict__ out) {
    __shared__ float tile[TF][TROW];       // 8 x 1028 floats
    __shared__ int   sj[SSTG];
    __shared__ float sv[SSTG];
    __shared__ int   sseg[TF + 1];

    int f0 = blockIdx.x * TF;
    int t  = threadIdx.x;                  // 0..255
    int g  = t >> 6;                       // feature group 0..3
    int u  = t & 63;                       // lane in group

    if (t <= TF) sseg[t] = g_seg[f0 + t];
    for (int k = t; k < TF * TROW; k += 256) ((float*)tile)[k] = 0.f;
    __syncthreads();

    int mbase = sseg[0];
    int total = sseg[TF] - mbase;
    const float4* up4 = (const float4*)g_upH;   // row = 128 float4 (1024 halves)

    if (total <= SSTG) {
        // ---- fast path: stage (j, v) once ----
        for (int k = t; k < total; k += 256) {
            sj[k] = jidx[mbase + k];
            sv[k] = g_vals[mbase + k];
        }
        __syncthreads();
#pragma unroll
        for (int lf = 2 * g; lf < 2 * g + 2; lf++) {
            int s0 = sseg[lf] - mbase, s1 = sseg[lf + 1] - mbase;
            float acc[16];
#pragma unroll
            for (int c = 0; c < 16; c++) acc[c] = 0.f;
#pragma unroll 4
            for (int k = s0; k < s1; k++) {
                float  v  = sv[k];
                size_t ro = (size_t)sj[k] * (NBS / 8);
                float4 r0 = up4[ro + 2 * u];
                float4 r1 = up4[ro + 2 * u + 1];
                fma8(acc, v, r0);
                fma8(acc + 8, v, r1);
            }
            float4* dst = (float4*)&tile[lf][16 * u];
            dst[0] = make_float4(acc[0],  acc[1],  acc[2],  acc[3]);
            dst[1] = make_float4(acc[4],  acc[5],  acc[6],  acc[7]);
            dst[2] = make_float4(acc[8],  acc[9],  acc[10], acc[11]);
            dst[3] = make_float4(acc[12], acc[13], acc[14], acc[15]);
        }
    } else {
        // ---- fallback: chunk-outer / feature-inner (CTA-uniform syncs) ----
        int mend = sseg[TF];
        for (int base = mbase; base < mend; base += SSTG) {
            int len = min(SSTG, mend - base);
            __syncthreads();
            for (int k = t; k < len; k += 256) {
                sj[k] = jidx[base + k];
                sv[k] = g_vals[base + k];
            }
            __syncthreads();
#pragma unroll
            for (int lf = 2 * g; lf < 2 * g + 2; lf++) {
                int s0 = max(sseg[lf], base) - base;
                int s1 = min(sseg[lf + 1], base + len) - base;
                float acc[16];
#pragma unroll
                for (int c = 0; c < 16; c++) acc[c] = 0.f;
                for (int k = s0; k < s1; k++) {
                    float  v  = sv[k];
                    size_t ro = (size_t)sj[k] * (NBS / 8);
                    float4 r0 = up4[ro + 2 * u];
                    float4 r1 = up4[ro + 2 * u + 1];
                    fma8(acc, v, r0);
                    fma8(acc + 8, v, r1);
                }
#pragma unroll
                for (int c = 0; c < 16; c++) tile[lf][16 * u + c] += acc[c];
            }
        }
    }
    __syncthreads();

    // Write 8 x 1024 tile to out[r][f0 + c]; tile read tile[c][r]:
    // addr = c*1028 + r -> bank (4c + r) % 32, all 32 distinct per warp.
    for (int idx = t; idx < TF * NBS; idx += 256) {
        int c = idx & (TF - 1);
        int r = idx >> 3;
        out[(size_t)r * NF + f0 + c] = tile[c][r];
    }
}

// ---------------------------------------------------------------------------
extern "C" void kernel_launch(void* const* d_in, const int* in_sizes, int n_in,
                              void* d_out, int out_size) {
    const float* up_facts = (const float*)d_in[0];  // [BS, F]
    const float* enc      = (const float*)d_in[1];  // [F, D]  down_encoder
    const float* dec      = (const float*)d_in[2];  // [D, F]  up_decoder
    const int*   iidx     = (const int*)d_in[3];    // [M] int32, sorted
    const int*   jidx     = (const int*)d_in[4];    // [M] int32
    float*       out      = (float*)d_out;          // [BS, F]

    __half* decH = nullptr; __half* upH = nullptr;
    cudaGetSymbolAddress((void**)&decH, g_decH);
    cudaGetSymbolAddress((void**)&upH,  g_upH);

    dim3 tb(32, 8);

    // 1. Dec [D,F] -> decH [F,D] fp16
    transpose32_h<<<dim3(NF / 32, ND / 32), tb>>>(dec, decH, ND, NF);
    // 2. up_facts [BS,F] -> upH [F,BS] fp16
    transpose32_h<<<dim3(NF / 32, NBS / 32), tb>>>(up_facts, upH, NBS, NF);
    // 3. segment starts
    segstart_kernel<<<(NF + 1 + 255) / 256, 256>>>(iidx);
    // 4. per-connection dot products
    values_kernel<<<(NM / VG) * 32 / 256, 256>>>(enc, iidx, jidx);
    // 5. fused segment reduction + transpose into out
    scatter_kernel<<<NF / TF, 256>>>(jidx, out);
}

// round 15
// speedup vs baseline: 1.0409x; 1.0409x over previous
#include <cuda_runtime.h>
#include <cuda_fp16.h>
#include <cstdint>

#define NF  16384   // n_features
#define ND  768     // d_model
#define NBS 1024    // B*S
#define NM  262144  // n_connections

// Scratch (device globals — no cudaMalloc allowed)
__device__ __align__(16) __half g_decH[(size_t)NF * ND];   // up_decoder transposed [F, D] fp16
__device__ __align__(16) __half g_upH [(size_t)NF * NBS];  // up_facts transposed  [F, BS] fp16
__device__ __align__(16) float  g_vals[NM];
__device__ int g_seg[NF + 1];

// ---------------------------------------------------------------------------
// 32x32 tiled transpose fp32 -> fp16
// ---------------------------------------------------------------------------
__global__ void transpose32_h(const float* __restrict__ in, __half* __restrict__ out,
                              int rows, int cols) {
    __shared__ float tile[32][33];
    int c0 = blockIdx.x * 32;
    int r0 = blockIdx.y * 32;
    int x = threadIdx.x, y = threadIdx.y;
#pragma unroll
    for (int k = 0; k < 32; k += 8)
        tile[y + k][x] = in[(size_t)(r0 + y + k) * cols + (c0 + x)];
    __syncthreads();
#pragma unroll
    for (int k = 0; k < 32; k += 8)
        out[(size_t)(c0 + y + k) * rows + (r0 + x)] = __float2half_rn(tile[x][y + k]);
}

// ---------------------------------------------------------------------------
// Segment boundaries: g_seg[f] = first m with i_indices[m] >= f (i sorted).
// ---------------------------------------------------------------------------
__global__ void segstart_kernel(const int* __restrict__ iidx) {
    int f = blockIdx.x * blockDim.x + threadIdx.x;
    if (f > NF) return;
    int lo = 0, hi = NM;
    while (lo < hi) {
        int mid = (lo + hi) >> 1;
        if (iidx[mid] < f) lo = mid + 1; else hi = mid;
    }
    g_seg[f] = lo;
}

// ---------------------------------------------------------------------------
// values v5 (measured 41.3us): warp per VG=16 consecutive connections; fp32
// Enc row cached in registers across equal sorted i; fp16 Dec rows (403MB
// L2 stream = the floor).
// ---------------------------------------------------------------------------
#define VG 16
__device__ __forceinline__ float dot8(float4 a_lo, float4 a_hi, float4 hraw, float s) {
    const __half2* h = (const __half2*)&hraw;
    float2 u0 = __half22float2(h[0]);
    float2 u1 = __half22float2(h[1]);
    float2 u2 = __half22float2(h[2]);
    float2 u3 = __half22float2(h[3]);
    s += a_lo.x * u0.x + a_lo.y * u0.y + a_lo.z * u1.x + a_lo.w * u1.y;
    s += a_hi.x * u2.x + a_hi.y * u2.y + a_hi.z * u3.x + a_hi.w * u3.y;
    return s;
}

__global__ void values_kernel(const float* __restrict__ enc,
                              const int* __restrict__ iidx,
                              const int* __restrict__ jidx) {
    int warp = (blockIdx.x * blockDim.x + threadIdx.x) >> 5;
    int lane = threadIdx.x & 31;
    int m0 = warp * VG;
    if (m0 >= NM) return;

    float4 a0, a1, a2, a3, a4, a5;
    int prev_i = -1;

#pragma unroll
    for (int g = 0; g < VG; g++) {
        int m = m0 + g;
        int i = iidx[m];
        int j = jidx[m];
        if (i != prev_i) {
            const float4* ap = (const float4*)(enc + (size_t)i * ND);
            a0 = ap[2 * lane];       a1 = ap[2 * lane + 1];
            a2 = ap[2 * lane + 64];  a3 = ap[2 * lane + 65];
            a4 = ap[2 * lane + 128]; a5 = ap[2 * lane + 129];
            prev_i = i;
        }
        const float4* bp = (const float4*)(g_decH + (size_t)j * ND);
        float4 q0 = bp[lane];
        float4 q1 = bp[lane + 32];
        float4 q2 = bp[lane + 64];

        float s = 0.f;
        s = dot8(a0, a1, q0, s);
        s = dot8(a2, a3, q1, s);
        s = dot8(a4, a5, q2, s);

#pragma unroll
        for (int off = 16; off; off >>= 1)
            s += __shfl_xor_sync(0xFFFFFFFFu, s, off);
        if (lane == 0) g_vals[m] = s;
    }
}

// ---------------------------------------------------------------------------
// Scatter v8 = v6 shape (best measured) + unroll 8.
// CTA = TF=8 features x full 1024 bs. 256 threads = 2 groups x 128:
//   group g handles features 4g..4g+3; thread u (0..127) owns columns
//   8u..8u+7 -> one float4 (8 halves, 16B) per connection; 128 x 16B = 2KB
//   full-row wavefront. Branch-free inner loops, unroll 8 -> 8 front-batched
//   LDG.128 per thread with only acc[8] live => no spill pressure.
// Output staged in padded smem tile, written directly in out[bs,f] layout.
// ---------------------------------------------------------------------------
#define TF    8
#define TROW  (NBS + 4)
#define SSTG  512

__device__ __forceinline__ void fma8(float* a, float v, float4 raw) {
    const __half2* h = (const __half2*)&raw;
    float2 u0 = __half22float2(h[0]);
    float2 u1 = __half22float2(h[1]);
    float2 u2 = __half22float2(h[2]);
    float2 u3 = __half22float2(h[3]);
    a[0] += v * u0.x; a[1] += v * u0.y;
    a[2] += v * u1.x; a[3] += v * u1.y;
    a[4] += v * u2.x; a[5] += v * u2.y;
    a[6] += v * u3.x; a[7] += v * u3.y;
}

__global__ void __launch_bounds__(256) scatter_kernel(const int* __restrict__ jidx,
                                                      float* __restrict__ out) {
    __shared__ float tile[TF][TROW];       // 8 x 1028 floats
    __shared__ int   sj[SSTG];
    __shared__ float sv[SSTG];
    __shared__ int   sseg[TF + 1];

    int f0 = blockIdx.x * TF;
    int t  = threadIdx.x;                  // 0..255
    int g  = t >> 7;                       // feature group 0/1
    int u  = t & 127;                      // lane in group

    if (t <= TF) sseg[t] = g_seg[f0 + t];
    for (int k = t; k < TF * TROW; k += 256) ((float*)tile)[k] = 0.f;
    __syncthreads();

    int mbase = sseg[0];
    int total = sseg[TF] - mbase;
    const float4* up4 = (const float4*)g_upH;   // row = 128 float4 (1024 halves)

    if (total <= SSTG) {
        // ---- fast path: stage (j, v) once ----
        for (int k = t; k < total; k += 256) {
            sj[k] = jidx[mbase + k];
            sv[k] = g_vals[mbase + k];
        }
        __syncthreads();
#pragma unroll
        for (int lf = 4 * g; lf < 4 * g + 4; lf++) {
            int s0 = sseg[lf] - mbase, s1 = sseg[lf + 1] - mbase;
            float acc[8] = {0.f, 0.f, 0.f, 0.f, 0.f, 0.f, 0.f, 0.f};
#pragma unroll 8
            for (int k = s0; k < s1; k++) {
                float  v   = sv[k];
                float4 raw = up4[(size_t)sj[k] * (NBS / 8) + u];
                fma8(acc, v, raw);
            }
            float4* dst = (float4*)&tile[lf][8 * u];
            dst[0] = make_float4(acc[0], acc[1], acc[2], acc[3]);
            dst[1] = make_float4(acc[4], acc[5], acc[6], acc[7]);
        }
    } else {
        // ---- fallback: chunk-outer / feature-inner (CTA-uniform syncs) ----
        int mend = sseg[TF];
        for (int base = mbase; base < mend; base += SSTG) {
            int len = min(SSTG, mend - base);
            __syncthreads();
            for (int k = t; k < len; k += 256) {
                sj[k] = jidx[base + k];
                sv[k] = g_vals[base + k];
            }
            __syncthreads();
#pragma unroll
            for (int lf = 4 * g; lf < 4 * g + 4; lf++) {
                int s0 = max(sseg[lf], base) - base;
                int s1 = min(sseg[lf + 1], base + len) - base;
                float acc[8] = {0.f, 0.f, 0.f, 0.f, 0.f, 0.f, 0.f, 0.f};
                for (int k = s0; k < s1; k++) {
                    float  v   = sv[k];
                    float4 raw = up4[(size_t)sj[k] * (NBS / 8) + u];
                    fma8(acc, v, raw);
                }
#pragma unroll
                for (int c = 0; c < 8; c++) tile[lf][8 * u + c] += acc[c];
            }
        }
    }
    __syncthreads();

    // Write 8 x 1024 tile to out[r][f0 + c]; tile read tile[c][r]:
    // addr = c*1028 + r -> bank (4c + r) % 32, all 32 distinct per warp.
    for (int idx = t; idx < TF * NBS; idx += 256) {
        int c = idx & (TF - 1);
        int r = idx >> 3;
        out[(size_t)r * NF + f0 + c] = tile[c][r];
    }
}

// ---------------------------------------------------------------------------
extern "C" void kernel_launch(void* const* d_in, const int* in_sizes, int n_in,
                              void* d_out, int out_size) {
    const float* up_facts = (const float*)d_in[0];  // [BS, F]
    const float* enc      = (const float*)d_in[1];  // [F, D]  down_encoder
    const float* dec      = (const float*)d_in[2];  // [D, F]  up_decoder
    const int*   iidx     = (const int*)d_in[3];    // [M] int32, sorted
    const int*   jidx     = (const int*)d_in[4];    // [M] int32
    float*       out      = (float*)d_out;          // [BS, F]

    __half* decH = nullptr; __half* upH = nullptr;
    cudaGetSymbolAddress((void**)&decH, g_decH);
    cudaGetSymbolAddress((void**)&upH,  g_upH);

    dim3 tb(32, 8);

    // 1. Dec [D,F] -> decH [F,D] fp16
    transpose32_h<<<dim3(NF / 32, ND / 32), tb>>>(dec, decH, ND, NF);
    // 2. up_facts [BS,F] -> upH [F,BS] fp16
    transpose32_h<<<dim3(NF / 32, NBS / 32), tb>>>(up_facts, upH, NBS, NF);
    // 3. segment starts
    segstart_kernel<<<(NF + 1 + 255) / 256, 256>>>(iidx);
    // 4. per-connection dot products
    values_kernel<<<(NM / VG) * 32 / 256, 256>>>(enc, iidx, jidx);
    // 5. fused segment reduction + transpose into out
    scatter_kernel<<<NF / TF, 256>>>(jidx, out);
}

// round 16
// speedup vs baseline: 1.0748x; 1.0325x over previous
#include <cuda_runtime.h>
#include <cuda_fp16.h>
#include <cstdint>

#define NF  16384   // n_features
#define ND  768     // d_model
#define NBS 1024    // B*S
#define NM  262144  // n_connections

// Scratch (device globals — no cudaMalloc allowed)
__device__ __align__(16) __half g_decH[(size_t)NF * ND];   // up_decoder transposed [F, D] fp16
__device__ __align__(16) __half g_upH [(size_t)NF * NBS];  // up_facts transposed  [F, BS] fp16
__device__ __align__(16) float  g_vals[NM];
__device__ int g_seg[NF + 1];

// ---------------------------------------------------------------------------
// Shared transpose body: 32x32 tile of in[rows][cols] -> out (fp16).
// ---------------------------------------------------------------------------
__device__ __forceinline__ void transpose_body_h(const float* __restrict__ in,
                                                 __half* __restrict__ out,
                                                 int rows, int cols,
                                                 int bx, int by,
                                                 float (*tile)[33]) {
    int c0 = bx * 32;
    int r0 = by * 32;
    int x = threadIdx.x, y = threadIdx.y;
#pragma unroll
    for (int k = 0; k < 32; k += 8)
        tile[y + k][x] = in[(size_t)(r0 + y + k) * cols + (c0 + x)];
    __syncthreads();
#pragma unroll
    for (int k = 0; k < 32; k += 8)
        out[(size_t)(c0 + y + k) * rows + (r0 + x)] = __float2half_rn(tile[x][y + k]);
}

// ---------------------------------------------------------------------------
// Kernel A: dec transpose (12288 blocks) ∪ segstart (65 blocks).
// blockDim = (32, 8).
// ---------------------------------------------------------------------------
#define NTD ((NF / 32) * (ND / 32))      // 12288
#define NSEG_BLK (((NF + 1) + 255) / 256)  // 65
__global__ void prep_kernel(const float* __restrict__ dec,
                            const int* __restrict__ iidx) {
    __shared__ float tile[32][33];
    if (blockIdx.x < NTD) {
        int bx = blockIdx.x % (NF / 32);
        int by = blockIdx.x / (NF / 32);
        transpose_body_h(dec, g_decH, ND, NF, bx, by, tile);
    } else {
        int t = threadIdx.y * 32 + threadIdx.x;
        int f = (blockIdx.x - NTD) * 256 + t;
        if (f > NF) return;
        int lo = 0, hi = NM;
        while (lo < hi) {
            int mid = (lo + hi) >> 1;
            if (iidx[mid] < f) lo = mid + 1; else hi = mid;
        }
        g_seg[f] = lo;
    }
}

// ---------------------------------------------------------------------------
// Kernel B: values (2048 blocks, FIRST so they schedule early) ∪ up transpose
// (16384 blocks). blockDim = (32, 8).
// values: warp per VG=16 consecutive connections; fp32 Enc row cached in
// registers across equal sorted i; fp16 Dec rows (403MB L2 stream = floor).
// ---------------------------------------------------------------------------
#define VG 16
#define NV_BLK (NM / VG / 8)             // 2048
#define NTU ((NF / 32) * (NBS / 32))     // 16384

__device__ __forceinline__ float dot8(float4 a_lo, float4 a_hi, float4 hraw, float s) {
    const __half2* h = (const __half2*)&hraw;
    float2 u0 = __half22float2(h[0]);
    float2 u1 = __half22float2(h[1]);
    float2 u2 = __half22float2(h[2]);
    float2 u3 = __half22float2(h[3]);
    s += a_lo.x * u0.x + a_lo.y * u0.y + a_lo.z * u1.x + a_lo.w * u1.y;
    s += a_hi.x * u2.x + a_hi.y * u2.y + a_hi.z * u3.x + a_hi.w * u3.y;
    return s;
}

__global__ void mid_kernel(const float* __restrict__ up_facts,
                           const float* __restrict__ enc,
                           const int* __restrict__ iidx,
                           const int* __restrict__ jidx) {
    __shared__ float tile[32][33];
    if (blockIdx.x >= NV_BLK) {
        int b  = blockIdx.x - NV_BLK;
        int bx = b % (NF / 32);
        int by = b / (NF / 32);
        transpose_body_h(up_facts, g_upH, NBS, NF, bx, by, tile);
        return;
    }

    // ---- values role ----
    int warp = blockIdx.x * 8 + threadIdx.y;
    int lane = threadIdx.x;
    int m0 = warp * VG;
    if (m0 >= NM) return;

    float4 a0, a1, a2, a3, a4, a5;
    int prev_i = -1;

#pragma unroll
    for (int g = 0; g < VG; g++) {
        int m = m0 + g;
        int i = iidx[m];
        int j = jidx[m];
        if (i != prev_i) {
            const float4* ap = (const float4*)(enc + (size_t)i * ND);
            a0 = ap[2 * lane];       a1 = ap[2 * lane + 1];
            a2 = ap[2 * lane + 64];  a3 = ap[2 * lane + 65];
            a4 = ap[2 * lane + 128]; a5 = ap[2 * lane + 129];
            prev_i = i;
        }
        const float4* bp = (const float4*)(g_decH + (size_t)j * ND);
        float4 q0 = bp[lane];
        float4 q1 = bp[lane + 32];
        float4 q2 = bp[lane + 64];

        float s = 0.f;
        s = dot8(a0, a1, q0, s);
        s = dot8(a2, a3, q1, s);
        s = dot8(a4, a5, q2, s);

#pragma unroll
        for (int off = 16; off; off >>= 1)
            s += __shfl_xor_sync(0xFFFFFFFFu, s, off);
        if (lane == 0) g_vals[m] = s;
    }
}

// ---------------------------------------------------------------------------
// Scatter v8 (best measured shape): fused segment-reduce + output transpose.
// CTA = TF=8 features x full 1024 bs. 256 threads = 2 groups x 128:
//   group g handles features 4g..4g+3; thread u (0..127) owns columns
//   8u..8u+7 -> one float4 (8 halves, 16B) per connection; 128 x 16B = 2KB
//   full-row wavefront. Branch-free inner loops, unroll 8.
// Output staged in padded smem tile, written directly in out[bs,f] layout.
// ---------------------------------------------------------------------------
#define TF    8
#define TROW  (NBS + 4)
#define SSTG  512

__device__ __forceinline__ void fma8(float* a, float v, float4 raw) {
    const __half2* h = (const __half2*)&raw;
    float2 u0 = __half22float2(h[0]);
    float2 u1 = __half22float2(h[1]);
    float2 u2 = __half22float2(h[2]);
    float2 u3 = __half22float2(h[3]);
    a[0] += v * u0.x; a[1] += v * u0.y;
    a[2] += v * u1.x; a[3] += v * u1.y;
    a[4] += v * u2.x; a[5] += v * u2.y;
    a[6] += v * u3.x; a[7] += v * u3.y;
}

__global__ void __launch_bounds__(256) scatter_kernel(const int* __restrict__ jidx,
                                                      float* __restrict__ out) {
    __shared__ float tile[TF][TROW];       // 8 x 1028 floats
    __shared__ int   sj[SSTG];
    __shared__ float sv[SSTG];
    __shared__ int   sseg[TF + 1];

    int f0 = blockIdx.x * TF;
    int t  = threadIdx.x;                  // 0..255
    int g  = t >> 7;                       // feature group 0/1
    int u  = t & 127;                      // lane in group

    if (t <= TF) sseg[t] = g_seg[f0 + t];
    for (int k = t; k < TF * TROW; k += 256) ((float*)tile)[k] = 0.f;
    __syncthreads();

    int mbase = sseg[0];
    int total = sseg[TF] - mbase;
    const float4* up4 = (const float4*)g_upH;   // row = 128 float4 (1024 halves)

    if (total <= SSTG) {
        // ---- fast path: stage (j, v) once ----
        for (int k = t; k < total; k += 256) {
            sj[k] = jidx[mbase + k];
            sv[k] = g_vals[mbase + k];
        }
        __syncthreads();
#pragma unroll
        for (int lf = 4 * g; lf < 4 * g + 4; lf++) {
            int s0 = sseg[lf] - mbase, s1 = sseg[lf + 1] - mbase;
            float acc[8] = {0.f, 0.f, 0.f, 0.f, 0.f, 0.f, 0.f, 0.f};
#pragma unroll 8
            for (int k = s0; k < s1; k++) {
                float  v   = sv[k];
                float4 raw = up4[(size_t)sj[k] * (NBS / 8) + u];
                fma8(acc, v, raw);
            }
            float4* dst = (float4*)&tile[lf][8 * u];
            dst[0] = make_float4(acc[0], acc[1], acc[2], acc[3]);
            dst[1] = make_float4(acc[4], acc[5], acc[6], acc[7]);
        }
    } else {
        // ---- fallback: chunk-outer / feature-inner (CTA-uniform syncs) ----
        int mend = sseg[TF];
        for (int base = mbase; base < mend; base += SSTG) {
            int len = min(SSTG, mend - base);
            __syncthreads();
            for (int k = t; k < len; k += 256) {
                sj[k] = jidx[base + k];
                sv[k] = g_vals[base + k];
            }
            __syncthreads();
#pragma unroll
            for (int lf = 4 * g; lf < 4 * g + 4; lf++) {
                int s0 = max(sseg[lf], base) - base;
                int s1 = min(sseg[lf + 1], base + len) - base;
                float acc[8] = {0.f, 0.f, 0.f, 0.f, 0.f, 0.f, 0.f, 0.f};
                for (int k = s0; k < s1; k++) {
                    float  v   = sv[k];
                    float4 raw = up4[(size_t)sj[k] * (NBS / 8) + u];
                    fma8(acc, v, raw);
                }
#pragma unroll
                for (int c = 0; c < 8; c++) tile[lf][8 * u + c] += acc[c];
            }
        }
    }
    __syncthreads();

    // Write 8 x 1024 tile to out[r][f0 + c]; tile read tile[c][r]:
    // addr = c*1028 + r -> bank (4c + r) % 32, all 32 distinct per warp.
    for (int idx = t; idx < TF * NBS; idx += 256) {
        int c = idx & (TF - 1);
        int r = idx >> 3;
        out[(size_t)r * NF + f0 + c] = tile[c][r];
    }
}

// ---------------------------------------------------------------------------
extern "C" void kernel_launch(void* const* d_in, const int* in_sizes, int n_in,
                              void* d_out, int out_size) {
    const float* up_facts = (const float*)d_in[0];  // [BS, F]
    const float* enc      = (const float*)d_in[1];  // [F, D]  down_encoder
    const float* dec      = (const float*)d_in[2];  // [D, F]  up_decoder
    const int*   iidx     = (const int*)d_in[3];    // [M] int32, sorted
    const int*   jidx     = (const int*)d_in[4];    // [M] int32
    float*       out      = (float*)d_out;          // [BS, F]

    dim3 tb(32, 8);

    // A: dec transpose ∪ segstart
    prep_kernel<<<NTD + NSEG_BLK, tb>>>(dec, iidx);
    // B: values ∪ up transpose (co-scheduled in one launch)
    mid_kernel<<<NV_BLK + NTU, tb>>>(up_facts, enc, iidx, jidx);
    // C: fused segment reduction + transpose into out
    scatter_kernel<<<NF / TF, 256>>>(jidx, out);
}